// round 7
// baseline (speedup 1.0000x reference)
#include <cuda_runtime.h>
#include <cstdint>
#include <math.h>

#define D_MODEL 1024
#define NHEAD 16
#define HEAD_DIM 64
#define BATCH 2
#define SEQ 2048
#define MTOT (BATCH*SEQ)   // 4096

// Scratch (allocation-free rule: __device__ globals)
__device__ float g_Q[MTOT * D_MODEL];
__device__ float g_K[MTOT * D_MODEL];
__device__ float g_V[MTOT * D_MODEL];
__device__ float g_Attn[MTOT * D_MODEL];
// tf32-pre-rounded copies of inputs / weights
__device__ float g_Xq[MTOT * D_MODEL];
__device__ float g_Xk[MTOT * D_MODEL];
__device__ float g_Xv[MTOT * D_MODEL];
__device__ float g_Wq[D_MODEL * D_MODEL];
__device__ float g_Wk[D_MODEL * D_MODEL];
__device__ float g_Wv[D_MODEL * D_MODEL];
__device__ float g_Wo[D_MODEL * D_MODEL];

// ---------------------------------------------------------------------------
// helpers
// ---------------------------------------------------------------------------
__device__ __forceinline__ unsigned f2tf(float x) {
    unsigned u;
    asm("cvt.rna.tf32.f32 %0, %1;" : "=r"(u) : "f"(x));
    return u;
}
__device__ __forceinline__ float f2tff(float x) { return __uint_as_float(f2tf(x)); }

__device__ __forceinline__ void mma8(float* c, const unsigned* a,
                                     unsigned b0, unsigned b1) {
    asm volatile(
        "mma.sync.aligned.m16n8k8.row.col.f32.tf32.tf32.f32 "
        "{%0,%1,%2,%3}, {%4,%5,%6,%7}, {%8,%9}, {%0,%1,%2,%3};"
        : "+f"(c[0]), "+f"(c[1]), "+f"(c[2]), "+f"(c[3])
        : "r"(a[0]), "r"(a[1]), "r"(a[2]), "r"(a[3]), "r"(b0), "r"(b1));
}

__device__ __forceinline__ void cp_async16(void* dst, const void* src) {
    unsigned int d = (unsigned int)__cvta_generic_to_shared(dst);
    asm volatile("cp.async.cg.shared.global [%0], [%1], 16;" :: "r"(d), "l"(src));
}
#define CP_COMMIT() asm volatile("cp.async.commit_group;")
#define CP_WAIT1()  asm volatile("cp.async.wait_group 1;")

// ---------------------------------------------------------------------------
// tf32 pre-rounding pass (idempotent)
// ---------------------------------------------------------------------------
__global__ void round_tf32_kernel(const float* __restrict__ src,
                                  float* __restrict__ dst)
{
    const int i = blockIdx.x * blockDim.x + threadIdx.x;
    float4 v = ((const float4*)src)[i];
    v.x = f2tff(v.x); v.y = f2tff(v.y); v.z = f2tff(v.z); v.w = f2tff(v.w);
    ((float4*)dst)[i] = v;
}

// ---------------------------------------------------------------------------
// tf32 GEMM, cp.async double-buffered:  C = (A @ W^T + bias) * scale
// A and W must be tf32-pre-rounded. Inner loop = LDS + HMMA only.
// 128x128 block, BK=32, 8 warps (2x4), warp tile 64x32, mma.m16n8k8.
// smem stride 36: fragment LDS conflict-free; cp.async dst 16B-aligned.
// ---------------------------------------------------------------------------
#define AS2 36
#define GEMM_SMEM (4 * 128 * AS2 * (int)sizeof(float))   // 73728 bytes

template<bool ROUND>
__global__ __launch_bounds__(256, 2) void gemm_cp(
    const float* __restrict__ A, const float* __restrict__ W,
    const float* __restrict__ bias, float scale, float* __restrict__ C)
{
    extern __shared__ float sm[];
    float* As = sm;                   // [2][128*AS2]
    float* Ws = sm + 2 * 128 * AS2;   // [2][128*AS2]

    const int m0 = blockIdx.y * 128;
    const int n0 = blockIdx.x * 128;
    const int t  = threadIdx.x;
    const int wid = t >> 5, lane = t & 31;
    const int g4 = lane >> 2, q4 = lane & 3;
    const int wm = wid >> 2;          // 0..1
    const int wn = wid & 3;           // 0..3
    const int lrow = t >> 1;          // 0..127
    const int lseg = (t & 1) * 16;

    float c[4][4][4];
    #pragma unroll
    for (int i = 0; i < 4; i++)
        #pragma unroll
        for (int j = 0; j < 4; j++)
            c[i][j][0] = c[i][j][1] = c[i][j][2] = c[i][j][3] = 0.f;

    const float* Ap = A + (size_t)(m0 + lrow) * D_MODEL + lseg;
    const float* Wp = W + (size_t)(n0 + lrow) * D_MODEL + lseg;

    // stage k-tile 0 into buf 0
    #pragma unroll
    for (int i = 0; i < 4; i++) {
        cp_async16(&As[lrow * AS2 + lseg + i * 4], Ap + i * 4);
        cp_async16(&Ws[lrow * AS2 + lseg + i * 4], Wp + i * 4);
    }
    CP_COMMIT();

    const int NKT = D_MODEL / 32;
    for (int kt = 0; kt < NKT; kt++) {
        if (kt + 1 < NKT) {
            float* An = As + ((kt + 1) & 1) * 128 * AS2;
            float* Wn = Ws + ((kt + 1) & 1) * 128 * AS2;
            const int k0 = (kt + 1) * 32;
            #pragma unroll
            for (int i = 0; i < 4; i++) {
                cp_async16(&An[lrow * AS2 + lseg + i * 4], Ap + k0 + i * 4);
                cp_async16(&Wn[lrow * AS2 + lseg + i * 4], Wp + k0 + i * 4);
            }
        }
        CP_COMMIT();
        CP_WAIT1();          // tile kt resident; kt+1 in flight
        __syncthreads();

        const float* Aw = As + (kt & 1) * 128 * AS2 + (wm * 64) * AS2;
        const float* Ww = Ws + (kt & 1) * 128 * AS2 + (wn * 32) * AS2;
        #pragma unroll
        for (int kk = 0; kk < 4; kk++) {
            unsigned a[4][4];
            #pragma unroll
            for (int i = 0; i < 4; i++) {
                const float* ap = Aw + (i * 16 + g4) * AS2 + kk * 8 + q4;
                a[i][0] = __float_as_uint(ap[0]);
                a[i][1] = __float_as_uint(ap[8 * AS2]);
                a[i][2] = __float_as_uint(ap[4]);
                a[i][3] = __float_as_uint(ap[8 * AS2 + 4]);
            }
            #pragma unroll
            for (int j = 0; j < 4; j++) {
                const float* bp = Ww + (j * 8 + g4) * AS2 + kk * 8 + q4;
                unsigned b0 = __float_as_uint(bp[0]);
                unsigned b1 = __float_as_uint(bp[4]);
                #pragma unroll
                for (int i = 0; i < 4; i++)
                    mma8(c[i][j], a[i], b0, b1);
            }
        }
        __syncthreads();   // readers done before next iter's cp.async overwrites
    }

    // ---- epilogue: direct STG from fragments, bias in registers ----
    #pragma unroll
    for (int j = 0; j < 4; j++) {
        const int col = n0 + wn * 32 + j * 8 + 2 * q4;
        const float2 bb = *(const float2*)&bias[col];
        #pragma unroll
        for (int i = 0; i < 4; i++) {
            const int row = m0 + wm * 64 + i * 16 + g4;
            float2 v0, v1;
            v0.x = (c[i][j][0] + bb.x) * scale;
            v0.y = (c[i][j][1] + bb.y) * scale;
            v1.x = (c[i][j][2] + bb.x) * scale;
            v1.y = (c[i][j][3] + bb.y) * scale;
            if (ROUND) {
                v0.x = f2tff(v0.x); v0.y = f2tff(v0.y);
                v1.x = f2tff(v1.x); v1.y = f2tff(v1.y);
            }
            *(float2*)&C[(size_t)row * D_MODEL + col] = v0;
            *(float2*)&C[(size_t)(row + 8) * D_MODEL + col] = v1;
        }
    }
}

// ---------------------------------------------------------------------------
// Flash attention, mma.sync m16n8k8 tf32, register accumulators.
// Q/K/V arrive tf32-pre-rounded. Output written tf32-rounded (feeds Wo GEMM).
// ---------------------------------------------------------------------------
#define KS 68
#define VS 72
#define PS 68
#define NTILES (SEQ / 64)
#define ATTN_SMEM ((128*PS + 2*64*KS + 2*64*VS) * (int)sizeof(float))  // 106496

__global__ __launch_bounds__(256, 2) void attn_mma(
    const float* __restrict__ Qb, const float* __restrict__ Kb,
    const float* __restrict__ Vb, float* __restrict__ Ob)
{
    extern __shared__ float sm[];
    float* Ps = sm;                         // [128][PS]  (Q staging, then P)
    float* Kbuf = Ps + 128 * PS;            // [2][64][KS]
    float* Vbuf = Kbuf + 2 * 64 * KS;       // [2][64][VS]

    const int qt = blockIdx.x, h = blockIdx.y, b = blockIdx.z;
    const int t = threadIdx.x, w = t >> 5, lane = t & 31;
    const int g4 = lane >> 2, q4 = lane & 3;
    const int base_q = b * SEQ + qt * 128;
    const int hcol = h * HEAD_DIM;

    // --- stage tile 0 of K/V via cp.async ---
    {
        const int base_k = b * SEQ;
        #pragma unroll
        for (int i = 0; i < 4; i++) {
            const int id = t + i * 256;
            const int row = id >> 4, seg = id & 15;
            const size_t g = (size_t)(base_k + row) * D_MODEL + hcol + seg * 4;
            cp_async16(&Kbuf[row * KS + seg * 4], Kb + g);
            cp_async16(&Vbuf[row * VS + seg * 4], Vb + g);
        }
    }
    CP_COMMIT();

    // --- stage Q and load A-fragments (already tf32 bit patterns) ---
    {
        const int r = t >> 1;
        const int c0 = (t & 1) * 32;
        #pragma unroll
        for (int i = 0; i < 8; i++)
            *(float4*)&Ps[r * PS + c0 + i * 4] =
                *(const float4*)&Qb[(size_t)(base_q + r) * D_MODEL + hcol + c0 + i * 4];
    }
    __syncwarp();

    unsigned qa[8][4];
    #pragma unroll
    for (int kk = 0; kk < 8; kk++) {
        qa[kk][0] = __float_as_uint(Ps[(w * 16 + g4)     * PS + kk * 8 + q4]);
        qa[kk][1] = __float_as_uint(Ps[(w * 16 + g4 + 8) * PS + kk * 8 + q4]);
        qa[kk][2] = __float_as_uint(Ps[(w * 16 + g4)     * PS + kk * 8 + q4 + 4]);
        qa[kk][3] = __float_as_uint(Ps[(w * 16 + g4 + 8) * PS + kk * 8 + q4 + 4]);
    }
    __syncwarp();   // Ps free for P reuse

    float of[8][4];
    #pragma unroll
    for (int n = 0; n < 8; n++)
        of[n][0] = of[n][1] = of[n][2] = of[n][3] = 0.f;
    float m0r = -1e30f, m1r = -1e30f, l0r = 0.f, l1r = 0.f;

    for (int jt = 0; jt < NTILES; jt++) {
        float* Kc = Kbuf + (jt & 1) * 64 * KS;
        float* Vc = Vbuf + (jt & 1) * 64 * VS;

        if (jt + 1 < NTILES) {
            float* Kn = Kbuf + ((jt + 1) & 1) * 64 * KS;
            float* Vn = Vbuf + ((jt + 1) & 1) * 64 * VS;
            const int base_k = b * SEQ + (jt + 1) * 64;
            #pragma unroll
            for (int i = 0; i < 4; i++) {
                const int id = t + i * 256;
                const int row = id >> 4, seg = id & 15;
                const size_t g = (size_t)(base_k + row) * D_MODEL + hcol + seg * 4;
                cp_async16(&Kn[row * KS + seg * 4], Kb + g);
                cp_async16(&Vn[row * VS + seg * 4], Vb + g);
            }
        }
        CP_COMMIT();
        CP_WAIT1();          // tile jt resident; jt+1 in flight
        __syncthreads();

        // ---- S = Q @ K^T ----
        float sfr[8][4];
        #pragma unroll
        for (int n = 0; n < 8; n++)
            sfr[n][0] = sfr[n][1] = sfr[n][2] = sfr[n][3] = 0.f;
        #pragma unroll
        for (int kk = 0; kk < 8; kk++) {
            #pragma unroll
            for (int n = 0; n < 8; n++) {
                const float* kp = &Kc[(n * 8 + g4) * KS + kk * 8 + q4];
                unsigned b0 = __float_as_uint(kp[0]);
                unsigned b1 = __float_as_uint(kp[4]);
                mma8(sfr[n], qa[kk], b0, b1);
            }
        }

        // ---- online softmax in registers ----
        float mx0 = -1e30f, mx1 = -1e30f;
        #pragma unroll
        for (int n = 0; n < 8; n++) {
            mx0 = fmaxf(mx0, fmaxf(sfr[n][0], sfr[n][1]));
            mx1 = fmaxf(mx1, fmaxf(sfr[n][2], sfr[n][3]));
        }
        mx0 = fmaxf(mx0, __shfl_xor_sync(0xffffffffu, mx0, 1));
        mx0 = fmaxf(mx0, __shfl_xor_sync(0xffffffffu, mx0, 2));
        mx1 = fmaxf(mx1, __shfl_xor_sync(0xffffffffu, mx1, 1));
        mx1 = fmaxf(mx1, __shfl_xor_sync(0xffffffffu, mx1, 2));

        const float mn0 = fmaxf(m0r, mx0);
        const float mn1 = fmaxf(m1r, mx1);
        const float a0 = __expf(m0r - mn0);
        const float a1 = __expf(m1r - mn1);
        m0r = mn0; m1r = mn1;

        float s0 = 0.f, s1 = 0.f;
        #pragma unroll
        for (int n = 0; n < 8; n++) {
            sfr[n][0] = __expf(sfr[n][0] - mn0);
            sfr[n][1] = __expf(sfr[n][1] - mn0);
            sfr[n][2] = __expf(sfr[n][2] - mn1);
            sfr[n][3] = __expf(sfr[n][3] - mn1);
            s0 += sfr[n][0] + sfr[n][1];
            s1 += sfr[n][2] + sfr[n][3];
            of[n][0] *= a0; of[n][1] *= a0;
            of[n][2] *= a1; of[n][3] *= a1;
            *(float2*)&Ps[(w * 16 + g4)     * PS + n * 8 + 2 * q4] =
                make_float2(sfr[n][0], sfr[n][1]);
            *(float2*)&Ps[(w * 16 + g4 + 8) * PS + n * 8 + 2 * q4] =
                make_float2(sfr[n][2], sfr[n][3]);
        }
        s0 += __shfl_xor_sync(0xffffffffu, s0, 1);
        s0 += __shfl_xor_sync(0xffffffffu, s0, 2);
        s1 += __shfl_xor_sync(0xffffffffu, s1, 1);
        s1 += __shfl_xor_sync(0xffffffffu, s1, 2);
        l0r = l0r * a0 + s0;
        l1r = l1r * a1 + s1;
        __syncwarp();

        // ---- O += P @ V ----
        #pragma unroll
        for (int kk = 0; kk < 8; kk++) {
            unsigned pa[4];
            pa[0] = f2tf(Ps[(w * 16 + g4)     * PS + kk * 8 + q4]);
            pa[1] = f2tf(Ps[(w * 16 + g4 + 8) * PS + kk * 8 + q4]);
            pa[2] = f2tf(Ps[(w * 16 + g4)     * PS + kk * 8 + q4 + 4]);
            pa[3] = f2tf(Ps[(w * 16 + g4 + 8) * PS + kk * 8 + q4 + 4]);
            #pragma unroll
            for (int n = 0; n < 8; n++) {
                unsigned b0 = __float_as_uint(Vc[(kk * 8 + q4)     * VS + n * 8 + g4]);
                unsigned b1 = __float_as_uint(Vc[(kk * 8 + q4 + 4) * VS + n * 8 + g4]);
                mma8(of[n], pa, b0, b1);
            }
        }
        __syncwarp();
        __syncthreads();   // all warps done with Kc/Vc before restaging
    }

    // ---- epilogue: normalize, round to tf32 (feeds Wo GEMM), write ----
    const float inv0 = 1.f / l0r;
    const float inv1 = 1.f / l1r;
    const int r0 = base_q + w * 16 + g4;
    #pragma unroll
    for (int n = 0; n < 8; n++) {
        const int c = hcol + n * 8 + 2 * q4;
        *(float2*)&Ob[(size_t)r0 * D_MODEL + c] =
            make_float2(f2tff(of[n][0] * inv0), f2tff(of[n][1] * inv0));
        *(float2*)&Ob[(size_t)(r0 + 8) * D_MODEL + c] =
            make_float2(f2tff(of[n][2] * inv1), f2tff(of[n][3] * inv1));
    }
}

// ---------------------------------------------------------------------------
extern "C" void kernel_launch(void* const* d_in, const int* in_sizes, int n_in,
                              void* d_out, int out_size)
{
    const float* query = (const float*)d_in[0];
    const float* key   = (const float*)d_in[1];
    const float* value = (const float*)d_in[2];
    const float* Wq    = (const float*)d_in[3];
    const float* bq    = (const float*)d_in[4];
    const float* Wk    = (const float*)d_in[5];
    const float* bk    = (const float*)d_in[6];
    const float* Wv    = (const float*)d_in[7];
    const float* bv    = (const float*)d_in[8];
    const float* Wo    = (const float*)d_in[9];
    const float* bo    = (const float*)d_in[10];
    float* out = (float*)d_out;

    float *pQ, *pK, *pV, *pA;
    float *pXq, *pXk, *pXv, *pWq, *pWk, *pWv, *pWo;
    cudaGetSymbolAddress((void**)&pQ, g_Q);
    cudaGetSymbolAddress((void**)&pK, g_K);
    cudaGetSymbolAddress((void**)&pV, g_V);
    cudaGetSymbolAddress((void**)&pA, g_Attn);
    cudaGetSymbolAddress((void**)&pXq, g_Xq);
    cudaGetSymbolAddress((void**)&pXk, g_Xk);
    cudaGetSymbolAddress((void**)&pXv, g_Xv);
    cudaGetSymbolAddress((void**)&pWq, g_Wq);
    cudaGetSymbolAddress((void**)&pWk, g_Wk);
    cudaGetSymbolAddress((void**)&pWv, g_Wv);
    cudaGetSymbolAddress((void**)&pWo, g_Wo);

    cudaFuncSetAttribute(gemm_cp<true>,
                         cudaFuncAttributeMaxDynamicSharedMemorySize, GEMM_SMEM);
    cudaFuncSetAttribute(gemm_cp<false>,
                         cudaFuncAttributeMaxDynamicSharedMemorySize, GEMM_SMEM);
    cudaFuncSetAttribute(attn_mma,
                         cudaFuncAttributeMaxDynamicSharedMemorySize, ATTN_SMEM);

    const int xb = (MTOT * D_MODEL / 4) / 256;     // 4096 blocks
    const int wb = (D_MODEL * D_MODEL / 4) / 256;  // 1024 blocks

    // --- tf32 pre-rounding (idempotent) ---
    round_tf32_kernel<<<xb, 256>>>(query, pXq);
    round_tf32_kernel<<<xb, 256>>>(key,   pXk);
    round_tf32_kernel<<<xb, 256>>>(value, pXv);
    round_tf32_kernel<<<wb, 256>>>(Wq, pWq);
    round_tf32_kernel<<<wb, 256>>>(Wk, pWk);
    round_tf32_kernel<<<wb, 256>>>(Wv, pWv);
    round_tf32_kernel<<<wb, 256>>>(Wo, pWo);

    dim3 gemm_grid(D_MODEL / 128, MTOT / 128);   // (8, 32)
    const float qscale = 0.125f;                 // 1/sqrt(64)

    gemm_cp<true><<<gemm_grid, 256, GEMM_SMEM>>>(pXq, pWq, bq, qscale, pQ);
    gemm_cp<true><<<gemm_grid, 256, GEMM_SMEM>>>(pXk, pWk, bk, 1.f,    pK);
    gemm_cp<true><<<gemm_grid, 256, GEMM_SMEM>>>(pXv, pWv, bv, 1.f,    pV);

    dim3 attn_grid(SEQ / 128, NHEAD, BATCH);     // (16, 16, 2)
    attn_mma<<<attn_grid, 256, ATTN_SMEM>>>(pQ, pK, pV, pA);

    gemm_cp<false><<<gemm_grid, 256, GEMM_SMEM>>>(pA, pWo, bo, 1.f, out);
}

// round 8
// speedup vs baseline: 1.0230x; 1.0230x over previous
#include <cuda_runtime.h>
#include <cstdint>
#include <math.h>

#define D_MODEL 1024
#define NHEAD 16
#define HEAD_DIM 64
#define BATCH 2
#define SEQ 2048
#define MTOT (BATCH*SEQ)   // 4096

// Scratch (allocation-free rule: __device__ globals)
__device__ float g_Q[MTOT * D_MODEL];
__device__ float g_K[MTOT * D_MODEL];
__device__ float g_V[MTOT * D_MODEL];
__device__ float g_Attn[MTOT * D_MODEL];

// ---------------------------------------------------------------------------
// helpers
// ---------------------------------------------------------------------------
__device__ __forceinline__ unsigned f2tf(float x) {
    unsigned u;
    asm("cvt.rna.tf32.f32 %0, %1;" : "=r"(u) : "f"(x));
    return u;
}
__device__ __forceinline__ float f2tff(float x) { return __uint_as_float(f2tf(x)); }

__device__ __forceinline__ void mma8(float* c, const unsigned* a,
                                     unsigned b0, unsigned b1) {
    asm volatile(
        "mma.sync.aligned.m16n8k8.row.col.f32.tf32.tf32.f32 "
        "{%0,%1,%2,%3}, {%4,%5,%6,%7}, {%8,%9}, {%0,%1,%2,%3};"
        : "+f"(c[0]), "+f"(c[1]), "+f"(c[2]), "+f"(c[3])
        : "r"(a[0]), "r"(a[1]), "r"(a[2]), "r"(a[3]), "r"(b0), "r"(b1));
}

__device__ __forceinline__ void cp_async16(void* dst, const void* src) {
    unsigned int d = (unsigned int)__cvta_generic_to_shared(dst);
    asm volatile("cp.async.cg.shared.global [%0], [%1], 16;" :: "r"(d), "l"(src));
}
#define CP_COMMIT() asm volatile("cp.async.commit_group;")
#define CP_WAIT1()  asm volatile("cp.async.wait_group 1;")

// ---------------------------------------------------------------------------
// Batched hand-rolled tf32 GEMM:  C_z = (A_z @ W_z^T + bias_z) * scale_z
// (z = blockIdx.z). 128x128 block, BK=32, 8 warps (2x4), warp tile 64x32,
// mma.m16n8k8. Operands tf32-rounded at staging; inner loop = LDS + HMMA.
// smem stride 36 -> fragment loads bank-conflict-free. One sync per k-tile.
// ---------------------------------------------------------------------------
#define AS2 36
#define GEMM_SMEM (4 * 128 * AS2 * (int)sizeof(float))   // 73728 bytes

struct GemmBatch {
    const float* A[3];
    const float* W[3];
    const float* bias[3];
    float scale[3];
    float* C[3];
};

template<bool ROUND>
__global__ __launch_bounds__(256, 2) void gemm_mma(GemmBatch gb)
{
    extern __shared__ float sm[];
    float* As = sm;                   // [2][128*AS2]
    float* Ws = sm + 2 * 128 * AS2;   // [2][128*AS2]

    const int z = blockIdx.z;
    const float* __restrict__ A = gb.A[z];
    const float* __restrict__ W = gb.W[z];
    const float* __restrict__ bias = gb.bias[z];
    const float scale = gb.scale[z];
    float* __restrict__ C = gb.C[z];

    const int m0 = blockIdx.y * 128;
    const int n0 = blockIdx.x * 128;
    const int t  = threadIdx.x;
    const int wid = t >> 5, lane = t & 31;
    const int g4 = lane >> 2, q4 = lane & 3;
    const int wm = wid >> 2;          // 0..1
    const int wn = wid & 3;           // 0..3
    const int lrow = t >> 1;          // 0..127
    const int lseg = (t & 1) * 16;

    float c[4][4][4];
    #pragma unroll
    for (int i = 0; i < 4; i++)
        #pragma unroll
        for (int j = 0; j < 4; j++)
            c[i][j][0] = c[i][j][1] = c[i][j][2] = c[i][j][3] = 0.f;

    const float* Ap = A + (size_t)(m0 + lrow) * D_MODEL + lseg;
    const float* Wp = W + (size_t)(n0 + lrow) * D_MODEL + lseg;

    // prologue: LDG tile 0
    float4 ra[4], rw[4];
    #pragma unroll
    for (int i = 0; i < 4; i++) {
        ra[i] = *(const float4*)(Ap + i * 4);
        rw[i] = *(const float4*)(Wp + i * 4);
    }

    const int NKT = D_MODEL / 32;
    for (int kt = 0; kt < NKT; kt++) {
        // STS tile kt (rounded to tf32) into buf kt&1
        float* Ab = As + (kt & 1) * 128 * AS2;
        float* Wb = Ws + (kt & 1) * 128 * AS2;
        #pragma unroll
        for (int i = 0; i < 4; i++) {
            float4 va = ra[i], vw = rw[i];
            va.x = f2tff(va.x); va.y = f2tff(va.y);
            va.z = f2tff(va.z); va.w = f2tff(va.w);
            vw.x = f2tff(vw.x); vw.y = f2tff(vw.y);
            vw.z = f2tff(vw.z); vw.w = f2tff(vw.w);
            *(float4*)&Ab[lrow * AS2 + lseg + i * 4] = va;
            *(float4*)&Wb[lrow * AS2 + lseg + i * 4] = vw;
        }
        __syncthreads();

        // LDG tile kt+1 (overlaps compute below)
        if (kt + 1 < NKT) {
            const int k0 = (kt + 1) * 32;
            #pragma unroll
            for (int i = 0; i < 4; i++) {
                ra[i] = *(const float4*)(Ap + k0 + i * 4);
                rw[i] = *(const float4*)(Wp + k0 + i * 4);
            }
        }

        // compute: 4 k8 steps
        const float* Aw = Ab + (wm * 64) * AS2;
        const float* Ww = Wb + (wn * 32) * AS2;
        #pragma unroll
        for (int kk = 0; kk < 4; kk++) {
            unsigned a[4][4];
            #pragma unroll
            for (int i = 0; i < 4; i++) {
                const float* ap = Aw + (i * 16 + g4) * AS2 + kk * 8 + q4;
                a[i][0] = __float_as_uint(ap[0]);
                a[i][1] = __float_as_uint(ap[8 * AS2]);
                a[i][2] = __float_as_uint(ap[4]);
                a[i][3] = __float_as_uint(ap[8 * AS2 + 4]);
            }
            #pragma unroll
            for (int j = 0; j < 4; j++) {
                const float* bp = Ww + (j * 8 + g4) * AS2 + kk * 8 + q4;
                unsigned b0 = __float_as_uint(bp[0]);
                unsigned b1 = __float_as_uint(bp[4]);
                #pragma unroll
                for (int i = 0; i < 4; i++)
                    mma8(c[i][j], a[i], b0, b1);
            }
        }
        // no trailing sync: next iter's STS targets the other buffer, whose
        // last readers were iter kt-1 (separated by this iter's sync).
    }

    // ---- epilogue: direct STG from fragments, bias in registers ----
    #pragma unroll
    for (int j = 0; j < 4; j++) {
        const int col = n0 + wn * 32 + j * 8 + 2 * q4;
        const float2 bb = *(const float2*)&bias[col];
        #pragma unroll
        for (int i = 0; i < 4; i++) {
            const int row = m0 + wm * 64 + i * 16 + g4;
            float2 v0, v1;
            v0.x = (c[i][j][0] + bb.x) * scale;
            v0.y = (c[i][j][1] + bb.y) * scale;
            v1.x = (c[i][j][2] + bb.x) * scale;
            v1.y = (c[i][j][3] + bb.y) * scale;
            if (ROUND) {
                v0.x = f2tff(v0.x); v0.y = f2tff(v0.y);
                v1.x = f2tff(v1.x); v1.y = f2tff(v1.y);
            }
            *(float2*)&C[(size_t)row * D_MODEL + col] = v0;
            *(float2*)&C[(size_t)(row + 8) * D_MODEL + col] = v1;
        }
    }
}

// ---------------------------------------------------------------------------
// Flash attention, mma.sync m16n8k8 tf32, register accumulators.
// Q/K/V arrive tf32-pre-rounded, so fragment loads are bit reinterprets.
// ---------------------------------------------------------------------------
#define KS 68
#define VS 72
#define PS 68
#define NTILES (SEQ / 64)
#define ATTN_SMEM ((128*PS + 2*64*KS + 2*64*VS) * (int)sizeof(float))  // 106496

__global__ __launch_bounds__(256, 2) void attn_mma(
    const float* __restrict__ Qb, const float* __restrict__ Kb,
    const float* __restrict__ Vb, float* __restrict__ Ob)
{
    extern __shared__ float sm[];
    float* Ps = sm;                         // [128][PS]  (Q staging, then P)
    float* Kbuf = Ps + 128 * PS;            // [2][64][KS]
    float* Vbuf = Kbuf + 2 * 64 * KS;       // [2][64][VS]

    const int qt = blockIdx.x, h = blockIdx.y, b = blockIdx.z;
    const int t = threadIdx.x, w = t >> 5, lane = t & 31;
    const int g4 = lane >> 2, q4 = lane & 3;
    const int base_q = b * SEQ + qt * 128;
    const int hcol = h * HEAD_DIM;

    // --- stage tile 0 of K/V via cp.async ---
    {
        const int base_k = b * SEQ;
        #pragma unroll
        for (int i = 0; i < 4; i++) {
            const int id = t + i * 256;
            const int row = id >> 4, seg = id & 15;
            const size_t g = (size_t)(base_k + row) * D_MODEL + hcol + seg * 4;
            cp_async16(&Kbuf[row * KS + seg * 4], Kb + g);
            cp_async16(&Vbuf[row * VS + seg * 4], Vb + g);
        }
    }
    CP_COMMIT();

    // --- stage Q and load A-fragments (already tf32 bit patterns) ---
    {
        const int r = t >> 1;
        const int c0 = (t & 1) * 32;
        #pragma unroll
        for (int i = 0; i < 8; i++)
            *(float4*)&Ps[r * PS + c0 + i * 4] =
                *(const float4*)&Qb[(size_t)(base_q + r) * D_MODEL + hcol + c0 + i * 4];
    }
    __syncwarp();

    unsigned qa[8][4];
    #pragma unroll
    for (int kk = 0; kk < 8; kk++) {
        qa[kk][0] = __float_as_uint(Ps[(w * 16 + g4)     * PS + kk * 8 + q4]);
        qa[kk][1] = __float_as_uint(Ps[(w * 16 + g4 + 8) * PS + kk * 8 + q4]);
        qa[kk][2] = __float_as_uint(Ps[(w * 16 + g4)     * PS + kk * 8 + q4 + 4]);
        qa[kk][3] = __float_as_uint(Ps[(w * 16 + g4 + 8) * PS + kk * 8 + q4 + 4]);
    }
    __syncwarp();   // Ps free for P reuse

    float of[8][4];
    #pragma unroll
    for (int n = 0; n < 8; n++)
        of[n][0] = of[n][1] = of[n][2] = of[n][3] = 0.f;
    float m0r = -1e30f, m1r = -1e30f, l0r = 0.f, l1r = 0.f;

    for (int jt = 0; jt < NTILES; jt++) {
        float* Kc = Kbuf + (jt & 1) * 64 * KS;
        float* Vc = Vbuf + (jt & 1) * 64 * VS;

        if (jt + 1 < NTILES) {
            float* Kn = Kbuf + ((jt + 1) & 1) * 64 * KS;
            float* Vn = Vbuf + ((jt + 1) & 1) * 64 * VS;
            const int base_k = b * SEQ + (jt + 1) * 64;
            #pragma unroll
            for (int i = 0; i < 4; i++) {
                const int id = t + i * 256;
                const int row = id >> 4, seg = id & 15;
                const size_t g = (size_t)(base_k + row) * D_MODEL + hcol + seg * 4;
                cp_async16(&Kn[row * KS + seg * 4], Kb + g);
                cp_async16(&Vn[row * VS + seg * 4], Vb + g);
            }
        }
        CP_COMMIT();
        CP_WAIT1();          // tile jt resident; jt+1 in flight
        __syncthreads();

        // ---- S = Q @ K^T ----
        float sfr[8][4];
        #pragma unroll
        for (int n = 0; n < 8; n++)
            sfr[n][0] = sfr[n][1] = sfr[n][2] = sfr[n][3] = 0.f;
        #pragma unroll
        for (int kk = 0; kk < 8; kk++) {
            #pragma unroll
            for (int n = 0; n < 8; n++) {
                const float* kp = &Kc[(n * 8 + g4) * KS + kk * 8 + q4];
                unsigned b0 = __float_as_uint(kp[0]);
                unsigned b1 = __float_as_uint(kp[4]);
                mma8(sfr[n], qa[kk], b0, b1);
            }
        }

        // ---- online softmax in registers ----
        float mx0 = -1e30f, mx1 = -1e30f;
        #pragma unroll
        for (int n = 0; n < 8; n++) {
            mx0 = fmaxf(mx0, fmaxf(sfr[n][0], sfr[n][1]));
            mx1 = fmaxf(mx1, fmaxf(sfr[n][2], sfr[n][3]));
        }
        mx0 = fmaxf(mx0, __shfl_xor_sync(0xffffffffu, mx0, 1));
        mx0 = fmaxf(mx0, __shfl_xor_sync(0xffffffffu, mx0, 2));
        mx1 = fmaxf(mx1, __shfl_xor_sync(0xffffffffu, mx1, 1));
        mx1 = fmaxf(mx1, __shfl_xor_sync(0xffffffffu, mx1, 2));

        const float mn0 = fmaxf(m0r, mx0);
        const float mn1 = fmaxf(m1r, mx1);
        const float a0 = __expf(m0r - mn0);
        const float a1 = __expf(m1r - mn1);
        m0r = mn0; m1r = mn1;

        float s0 = 0.f, s1 = 0.f;
        #pragma unroll
        for (int n = 0; n < 8; n++) {
            sfr[n][0] = __expf(sfr[n][0] - mn0);
            sfr[n][1] = __expf(sfr[n][1] - mn0);
            sfr[n][2] = __expf(sfr[n][2] - mn1);
            sfr[n][3] = __expf(sfr[n][3] - mn1);
            s0 += sfr[n][0] + sfr[n][1];
            s1 += sfr[n][2] + sfr[n][3];
            of[n][0] *= a0; of[n][1] *= a0;
            of[n][2] *= a1; of[n][3] *= a1;
            *(float2*)&Ps[(w * 16 + g4)     * PS + n * 8 + 2 * q4] =
                make_float2(sfr[n][0], sfr[n][1]);
            *(float2*)&Ps[(w * 16 + g4 + 8) * PS + n * 8 + 2 * q4] =
                make_float2(sfr[n][2], sfr[n][3]);
        }
        s0 += __shfl_xor_sync(0xffffffffu, s0, 1);
        s0 += __shfl_xor_sync(0xffffffffu, s0, 2);
        s1 += __shfl_xor_sync(0xffffffffu, s1, 1);
        s1 += __shfl_xor_sync(0xffffffffu, s1, 2);
        l0r = l0r * a0 + s0;
        l1r = l1r * a1 + s1;
        __syncwarp();

        // ---- O += P @ V ----
        #pragma unroll
        for (int kk = 0; kk < 8; kk++) {
            unsigned pa[4];
            pa[0] = f2tf(Ps[(w * 16 + g4)     * PS + kk * 8 + q4]);
            pa[1] = f2tf(Ps[(w * 16 + g4 + 8) * PS + kk * 8 + q4]);
            pa[2] = f2tf(Ps[(w * 16 + g4)     * PS + kk * 8 + q4 + 4]);
            pa[3] = f2tf(Ps[(w * 16 + g4 + 8) * PS + kk * 8 + q4 + 4]);
            #pragma unroll
            for (int n = 0; n < 8; n++) {
                unsigned b0 = __float_as_uint(Vc[(kk * 8 + q4)     * VS + n * 8 + g4]);
                unsigned b1 = __float_as_uint(Vc[(kk * 8 + q4 + 4) * VS + n * 8 + g4]);
                mma8(of[n], pa, b0, b1);
            }
        }
        __syncwarp();
        __syncthreads();   // all warps done with Kc/Vc before restaging
    }

    // ---- epilogue: normalize, write [B,T,H*hd] ----
    const float inv0 = 1.f / l0r;
    const float inv1 = 1.f / l1r;
    const int r0 = base_q + w * 16 + g4;
    #pragma unroll
    for (int n = 0; n < 8; n++) {
        const int c = hcol + n * 8 + 2 * q4;
        *(float2*)&Ob[(size_t)r0 * D_MODEL + c] =
            make_float2(of[n][0] * inv0, of[n][1] * inv0);
        *(float2*)&Ob[(size_t)(r0 + 8) * D_MODEL + c] =
            make_float2(of[n][2] * inv1, of[n][3] * inv1);
    }
}

// ---------------------------------------------------------------------------
extern "C" void kernel_launch(void* const* d_in, const int* in_sizes, int n_in,
                              void* d_out, int out_size)
{
    const float* query = (const float*)d_in[0];
    const float* key   = (const float*)d_in[1];
    const float* value = (const float*)d_in[2];
    const float* Wq    = (const float*)d_in[3];
    const float* bq    = (const float*)d_in[4];
    const float* Wk    = (const float*)d_in[5];
    const float* bk    = (const float*)d_in[6];
    const float* Wv    = (const float*)d_in[7];
    const float* bv    = (const float*)d_in[8];
    const float* Wo    = (const float*)d_in[9];
    const float* bo    = (const float*)d_in[10];
    float* out = (float*)d_out;

    float *pQ, *pK, *pV, *pA;
    cudaGetSymbolAddress((void**)&pQ, g_Q);
    cudaGetSymbolAddress((void**)&pK, g_K);
    cudaGetSymbolAddress((void**)&pV, g_V);
    cudaGetSymbolAddress((void**)&pA, g_Attn);

    cudaFuncSetAttribute(gemm_mma<true>,
                         cudaFuncAttributeMaxDynamicSharedMemorySize, GEMM_SMEM);
    cudaFuncSetAttribute(gemm_mma<false>,
                         cudaFuncAttributeMaxDynamicSharedMemorySize, GEMM_SMEM);
    cudaFuncSetAttribute(attn_mma,
                         cudaFuncAttributeMaxDynamicSharedMemorySize, ATTN_SMEM);

    const float qscale = 0.125f;                 // 1/sqrt(64)

    // --- fused Q/K/V projection: one launch, blockIdx.z = which GEMM ---
    GemmBatch proj;
    proj.A[0] = query; proj.W[0] = Wq; proj.bias[0] = bq; proj.scale[0] = qscale; proj.C[0] = pQ;
    proj.A[1] = key;   proj.W[1] = Wk; proj.bias[1] = bk; proj.scale[1] = 1.f;    proj.C[1] = pK;
    proj.A[2] = value; proj.W[2] = Wv; proj.bias[2] = bv; proj.scale[2] = 1.f;    proj.C[2] = pV;

    dim3 proj_grid(D_MODEL / 128, MTOT / 128, 3);   // (8, 32, 3) = 768 CTAs
    gemm_mma<true><<<proj_grid, 256, GEMM_SMEM>>>(proj);

    // --- attention ---
    dim3 attn_grid(SEQ / 128, NHEAD, BATCH);        // (16, 16, 2)
    attn_mma<<<attn_grid, 256, ATTN_SMEM>>>(pQ, pK, pV, pA);

    // --- output projection ---
    GemmBatch outb;
    outb.A[0] = pA; outb.W[0] = Wo; outb.bias[0] = bo; outb.scale[0] = 1.f; outb.C[0] = out;
    outb.A[1] = outb.A[2] = nullptr; outb.W[1] = outb.W[2] = nullptr;
    outb.bias[1] = outb.bias[2] = nullptr; outb.scale[1] = outb.scale[2] = 0.f;
    outb.C[1] = outb.C[2] = nullptr;

    dim3 out_grid(D_MODEL / 128, MTOT / 128, 1);    // (8, 32, 1)
    gemm_mma<false><<<out_grid, 256, GEMM_SMEM>>>(outb);
}

// round 9
// speedup vs baseline: 1.1642x; 1.1380x over previous
#include <cuda_runtime.h>
#include <cstdint>
#include <math.h>

#define D_MODEL 1024
#define NHEAD 16
#define HEAD_DIM 64
#define BATCH 2
#define SEQ 2048
#define MTOT (BATCH*SEQ)   // 4096

// Scratch (allocation-free rule: __device__ globals)
__device__ float g_Q[MTOT * D_MODEL];
__device__ float g_K[MTOT * D_MODEL];
__device__ float g_V[MTOT * D_MODEL];
__device__ float g_Attn[MTOT * D_MODEL];

// ---------------------------------------------------------------------------
// helpers
// ---------------------------------------------------------------------------
__device__ __forceinline__ unsigned f2tf(float x) {
    unsigned u;
    asm("cvt.rna.tf32.f32 %0, %1;" : "=r"(u) : "f"(x));
    return u;
}
__device__ __forceinline__ float f2tff(float x) { return __uint_as_float(f2tf(x)); }

__device__ __forceinline__ void mma8(float* c, const unsigned* a,
                                     unsigned b0, unsigned b1) {
    asm volatile(
        "mma.sync.aligned.m16n8k8.row.col.f32.tf32.tf32.f32 "
        "{%0,%1,%2,%3}, {%4,%5,%6,%7}, {%8,%9}, {%0,%1,%2,%3};"
        : "+f"(c[0]), "+f"(c[1]), "+f"(c[2]), "+f"(c[3])
        : "r"(a[0]), "r"(a[1]), "r"(a[2]), "r"(a[3]), "r"(b0), "r"(b1));
}

// ldmatrix x4: 4 8x8 b16 matrices; for tf32 each 32-bit result = one fp32 elem.
__device__ __forceinline__ void ldsm4(unsigned& r0, unsigned& r1,
                                      unsigned& r2, unsigned& r3, const void* p) {
    unsigned addr = (unsigned)__cvta_generic_to_shared(p);
    asm volatile("ldmatrix.sync.aligned.m8n8.x4.shared.b16 {%0,%1,%2,%3}, [%4];"
        : "=r"(r0), "=r"(r1), "=r"(r2), "=r"(r3) : "r"(addr));
}

__device__ __forceinline__ void cp_async16(void* dst, const void* src) {
    unsigned int d = (unsigned int)__cvta_generic_to_shared(dst);
    asm volatile("cp.async.cg.shared.global [%0], [%1], 16;" :: "r"(d), "l"(src));
}
#define CP_COMMIT() asm volatile("cp.async.commit_group;")
#define CP_WAIT1()  asm volatile("cp.async.wait_group 1;")

// ---------------------------------------------------------------------------
// Hand-rolled tf32 GEMM:  C = (A @ W^T + bias) * scale  [tf32-round if ROUND]
// 128x128 block, BK=32, 8 warps (2x4), warp tile 64x32, mma.m16n8k8.
// Operands rounded to tf32 at staging; inner loop = LDSM + HMMA only.
// smem stride 36 -> 4-bank row step: every ldmatrix phase conflict-free.
// ---------------------------------------------------------------------------
#define AS2 36
#define GEMM_SMEM (4 * 128 * AS2 * (int)sizeof(float))   // 73728 bytes

template<bool ROUND>
__global__ __launch_bounds__(256, 2) void gemm_mma(
    const float* __restrict__ A, const float* __restrict__ W,
    const float* __restrict__ bias, float scale, float* __restrict__ C)
{
    extern __shared__ float sm[];
    float* As = sm;                   // [2][128*AS2]
    float* Ws = sm + 2 * 128 * AS2;   // [2][128*AS2]

    const int m0 = blockIdx.y * 128;
    const int n0 = blockIdx.x * 128;
    const int t  = threadIdx.x;
    const int wid = t >> 5, lane = t & 31;
    const int g4 = lane >> 2, q4 = lane & 3;
    const int wm = wid >> 2;          // 0..1
    const int wn = wid & 3;           // 0..3
    const int lrow = t >> 1;          // 0..127
    const int lseg = (t & 1) * 16;

    float c[4][4][4];
    #pragma unroll
    for (int i = 0; i < 4; i++)
        #pragma unroll
        for (int j = 0; j < 4; j++)
            c[i][j][0] = c[i][j][1] = c[i][j][2] = c[i][j][3] = 0.f;

    const float* Ap = A + (size_t)(m0 + lrow) * D_MODEL + lseg;
    const float* Wp = W + (size_t)(n0 + lrow) * D_MODEL + lseg;

    // ldmatrix per-lane address components
    const int aoff = (lane & 15) * AS2 + (lane >> 4) * 4;                    // A/x4
    const int boff = ((lane & 7) + (lane >> 4) * 8) * AS2 + ((lane >> 3) & 1) * 4; // B-pair/x4

    // prologue: LDG tile 0
    float4 ra[4], rw[4];
    #pragma unroll
    for (int i = 0; i < 4; i++) {
        ra[i] = *(const float4*)(Ap + i * 4);
        rw[i] = *(const float4*)(Wp + i * 4);
    }

    const int NKT = D_MODEL / 32;
    for (int kt = 0; kt < NKT; kt++) {
        // STS tile kt (rounded to tf32) into buf kt&1
        float* Ab = As + (kt & 1) * 128 * AS2;
        float* Wb = Ws + (kt & 1) * 128 * AS2;
        #pragma unroll
        for (int i = 0; i < 4; i++) {
            float4 va = ra[i], vw = rw[i];
            va.x = f2tff(va.x); va.y = f2tff(va.y);
            va.z = f2tff(va.z); va.w = f2tff(va.w);
            vw.x = f2tff(vw.x); vw.y = f2tff(vw.y);
            vw.z = f2tff(vw.z); vw.w = f2tff(vw.w);
            *(float4*)&Ab[lrow * AS2 + lseg + i * 4] = va;
            *(float4*)&Wb[lrow * AS2 + lseg + i * 4] = vw;
        }
        __syncthreads();

        // LDG tile kt+1 (overlaps compute below)
        if (kt + 1 < NKT) {
            const int k0 = (kt + 1) * 32;
            #pragma unroll
            for (int i = 0; i < 4; i++) {
                ra[i] = *(const float4*)(Ap + k0 + i * 4);
                rw[i] = *(const float4*)(Wp + k0 + i * 4);
            }
        }

        // compute: 4 k8 steps, fragments via ldmatrix
        const float* aB = Ab + (wm * 64) * AS2 + aoff;
        const float* bB = Wb + (wn * 32) * AS2 + boff;
        #pragma unroll
        for (int kk = 0; kk < 4; kk++) {
            unsigned a[4][4];
            #pragma unroll
            for (int i = 0; i < 4; i++)
                ldsm4(a[i][0], a[i][1], a[i][2], a[i][3],
                      aB + i * 16 * AS2 + kk * 8);
            unsigned rb[8];
            ldsm4(rb[0], rb[1], rb[2], rb[3], bB + kk * 8);             // j=0,1
            ldsm4(rb[4], rb[5], rb[6], rb[7], bB + 16 * AS2 + kk * 8);  // j=2,3
            #pragma unroll
            for (int j = 0; j < 4; j++) {
                #pragma unroll
                for (int i = 0; i < 4; i++)
                    mma8(c[i][j], a[i], rb[j * 2], rb[j * 2 + 1]);
            }
        }
        // no trailing sync: next iter's STS targets the other buffer, whose
        // last readers were iter kt-1 (separated by this iter's sync).
    }

    // ---- epilogue: direct STG from fragments, bias in registers ----
    #pragma unroll
    for (int j = 0; j < 4; j++) {
        const int col = n0 + wn * 32 + j * 8 + 2 * q4;
        const float2 bb = *(const float2*)&bias[col];
        #pragma unroll
        for (int i = 0; i < 4; i++) {
            const int row = m0 + wm * 64 + i * 16 + g4;
            float2 v0, v1;
            v0.x = (c[i][j][0] + bb.x) * scale;
            v0.y = (c[i][j][1] + bb.y) * scale;
            v1.x = (c[i][j][2] + bb.x) * scale;
            v1.y = (c[i][j][3] + bb.y) * scale;
            if (ROUND) {
                v0.x = f2tff(v0.x); v0.y = f2tff(v0.y);
                v1.x = f2tff(v1.x); v1.y = f2tff(v1.y);
            }
            *(float2*)&C[(size_t)row * D_MODEL + col] = v0;
            *(float2*)&C[(size_t)(row + 8) * D_MODEL + col] = v1;
        }
    }
}

// ---------------------------------------------------------------------------
// Flash attention, mma.sync m16n8k8 tf32, register accumulators.
// Q/K/V arrive tf32-pre-rounded. K and P fragments loaded via ldmatrix.
// ---------------------------------------------------------------------------
#define KS 68
#define VS 72
#define PS 68
#define NTILES (SEQ / 64)
#define ATTN_SMEM ((128*PS + 2*64*KS + 2*64*VS) * (int)sizeof(float))  // 106496

__global__ __launch_bounds__(256, 2) void attn_mma(
    const float* __restrict__ Qb, const float* __restrict__ Kb,
    const float* __restrict__ Vb, float* __restrict__ Ob)
{
    extern __shared__ float sm[];
    float* Ps = sm;                         // [128][PS]  (Q staging, then P)
    float* Kbuf = Ps + 128 * PS;            // [2][64][KS]
    float* Vbuf = Kbuf + 2 * 64 * KS;       // [2][64][VS]

    const int qt = blockIdx.x, h = blockIdx.y, b = blockIdx.z;
    const int t = threadIdx.x, w = t >> 5, lane = t & 31;
    const int g4 = lane >> 2, q4 = lane & 3;
    const int base_q = b * SEQ + qt * 128;
    const int hcol = h * HEAD_DIM;

    // ldmatrix per-lane address components
    const int koff = ((lane & 7) + (lane >> 4) * 8) * KS + ((lane >> 3) & 1) * 4;  // K-pair
    const int poff = (lane & 15) * PS + (lane >> 4) * 4;                            // P/x4

    // --- stage tile 0 of K/V via cp.async ---
    {
        const int base_k = b * SEQ;
        #pragma unroll
        for (int i = 0; i < 4; i++) {
            const int id = t + i * 256;
            const int row = id >> 4, seg = id & 15;
            const size_t g = (size_t)(base_k + row) * D_MODEL + hcol + seg * 4;
            cp_async16(&Kbuf[row * KS + seg * 4], Kb + g);
            cp_async16(&Vbuf[row * VS + seg * 4], Vb + g);
        }
    }
    CP_COMMIT();

    // --- stage Q and load A-fragments (already tf32 bit patterns) ---
    {
        const int r = t >> 1;
        const int c0 = (t & 1) * 32;
        #pragma unroll
        for (int i = 0; i < 8; i++)
            *(float4*)&Ps[r * PS + c0 + i * 4] =
                *(const float4*)&Qb[(size_t)(base_q + r) * D_MODEL + hcol + c0 + i * 4];
    }
    __syncwarp();

    unsigned qa[8][4];
    {
        const float* qB = Ps + (w * 16) * PS + poff;
        #pragma unroll
        for (int kk = 0; kk < 8; kk++)
            ldsm4(qa[kk][0], qa[kk][1], qa[kk][2], qa[kk][3], qB + kk * 8);
    }
    __syncwarp();   // Ps free for P reuse

    float of[8][4];
    #pragma unroll
    for (int n = 0; n < 8; n++)
        of[n][0] = of[n][1] = of[n][2] = of[n][3] = 0.f;
    float m0r = -1e30f, m1r = -1e30f, l0r = 0.f, l1r = 0.f;

    for (int jt = 0; jt < NTILES; jt++) {
        float* Kc = Kbuf + (jt & 1) * 64 * KS;
        float* Vc = Vbuf + (jt & 1) * 64 * VS;

        if (jt + 1 < NTILES) {
            float* Kn = Kbuf + ((jt + 1) & 1) * 64 * KS;
            float* Vn = Vbuf + ((jt + 1) & 1) * 64 * VS;
            const int base_k = b * SEQ + (jt + 1) * 64;
            #pragma unroll
            for (int i = 0; i < 4; i++) {
                const int id = t + i * 256;
                const int row = id >> 4, seg = id & 15;
                const size_t g = (size_t)(base_k + row) * D_MODEL + hcol + seg * 4;
                cp_async16(&Kn[row * KS + seg * 4], Kb + g);
                cp_async16(&Vn[row * VS + seg * 4], Vb + g);
            }
        }
        CP_COMMIT();
        CP_WAIT1();          // tile jt resident; jt+1 in flight
        __syncthreads();

        // ---- S = Q @ K^T  (K fragments via ldmatrix, 2 n-blocks per op) ----
        float sfr[8][4];
        #pragma unroll
        for (int n = 0; n < 8; n++)
            sfr[n][0] = sfr[n][1] = sfr[n][2] = sfr[n][3] = 0.f;
        {
            const float* kB = Kc + koff;
            #pragma unroll
            for (int kk = 0; kk < 8; kk++) {
                #pragma unroll
                for (int jp = 0; jp < 4; jp++) {
                    unsigned rb[4];
                    ldsm4(rb[0], rb[1], rb[2], rb[3], kB + jp * 16 * KS + kk * 8);
                    mma8(sfr[jp * 2],     qa[kk], rb[0], rb[1]);
                    mma8(sfr[jp * 2 + 1], qa[kk], rb[2], rb[3]);
                }
            }
        }

        // ---- online softmax in registers ----
        float mx0 = -1e30f, mx1 = -1e30f;
        #pragma unroll
        for (int n = 0; n < 8; n++) {
            mx0 = fmaxf(mx0, fmaxf(sfr[n][0], sfr[n][1]));
            mx1 = fmaxf(mx1, fmaxf(sfr[n][2], sfr[n][3]));
        }
        mx0 = fmaxf(mx0, __shfl_xor_sync(0xffffffffu, mx0, 1));
        mx0 = fmaxf(mx0, __shfl_xor_sync(0xffffffffu, mx0, 2));
        mx1 = fmaxf(mx1, __shfl_xor_sync(0xffffffffu, mx1, 1));
        mx1 = fmaxf(mx1, __shfl_xor_sync(0xffffffffu, mx1, 2));

        const float mn0 = fmaxf(m0r, mx0);
        const float mn1 = fmaxf(m1r, mx1);
        const float a0 = __expf(m0r - mn0);
        const float a1 = __expf(m1r - mn1);
        m0r = mn0; m1r = mn1;

        float s0 = 0.f, s1 = 0.f;
        #pragma unroll
        for (int n = 0; n < 8; n++) {
            sfr[n][0] = __expf(sfr[n][0] - mn0);
            sfr[n][1] = __expf(sfr[n][1] - mn0);
            sfr[n][2] = __expf(sfr[n][2] - mn1);
            sfr[n][3] = __expf(sfr[n][3] - mn1);
            s0 += sfr[n][0] + sfr[n][1];
            s1 += sfr[n][2] + sfr[n][3];
            of[n][0] *= a0; of[n][1] *= a0;
            of[n][2] *= a1; of[n][3] *= a1;
            *(float2*)&Ps[(w * 16 + g4)     * PS + n * 8 + 2 * q4] =
                make_float2(sfr[n][0], sfr[n][1]);
            *(float2*)&Ps[(w * 16 + g4 + 8) * PS + n * 8 + 2 * q4] =
                make_float2(sfr[n][2], sfr[n][3]);
        }
        s0 += __shfl_xor_sync(0xffffffffu, s0, 1);
        s0 += __shfl_xor_sync(0xffffffffu, s0, 2);
        s1 += __shfl_xor_sync(0xffffffffu, s1, 1);
        s1 += __shfl_xor_sync(0xffffffffu, s1, 2);
        l0r = l0r * a0 + s0;
        l1r = l1r * a1 + s1;
        __syncwarp();

        // ---- O += P @ V  (P fragments via ldmatrix + cvt) ----
        {
            const float* pB = Ps + (w * 16) * PS + poff;
            #pragma unroll
            for (int kk = 0; kk < 8; kk++) {
                unsigned r0, r1, r2, r3;
                ldsm4(r0, r1, r2, r3, pB + kk * 8);
                unsigned pa[4];
                pa[0] = f2tf(__uint_as_float(r0));
                pa[1] = f2tf(__uint_as_float(r1));
                pa[2] = f2tf(__uint_as_float(r2));
                pa[3] = f2tf(__uint_as_float(r3));
                #pragma unroll
                for (int n = 0; n < 8; n++) {
                    unsigned b0 = __float_as_uint(Vc[(kk * 8 + q4)     * VS + n * 8 + g4]);
                    unsigned b1 = __float_as_uint(Vc[(kk * 8 + q4 + 4) * VS + n * 8 + g4]);
                    mma8(of[n], pa, b0, b1);
                }
            }
        }
        __syncwarp();
        __syncthreads();   // all warps done with Kc/Vc before restaging
    }

    // ---- epilogue: normalize, write [B,T,H*hd] ----
    const float inv0 = 1.f / l0r;
    const float inv1 = 1.f / l1r;
    const int r0 = base_q + w * 16 + g4;
    #pragma unroll
    for (int n = 0; n < 8; n++) {
        const int c = hcol + n * 8 + 2 * q4;
        *(float2*)&Ob[(size_t)r0 * D_MODEL + c] =
            make_float2(of[n][0] * inv0, of[n][1] * inv0);
        *(float2*)&Ob[(size_t)(r0 + 8) * D_MODEL + c] =
            make_float2(of[n][2] * inv1, of[n][3] * inv1);
    }
}

// ---------------------------------------------------------------------------
extern "C" void kernel_launch(void* const* d_in, const int* in_sizes, int n_in,
                              void* d_out, int out_size)
{
    const float* query = (const float*)d_in[0];
    const float* key   = (const float*)d_in[1];
    const float* value = (const float*)d_in[2];
    const float* Wq    = (const float*)d_in[3];
    const float* bq    = (const float*)d_in[4];
    const float* Wk    = (const float*)d_in[5];
    const float* bk    = (const float*)d_in[6];
    const float* Wv    = (const float*)d_in[7];
    const float* bv    = (const float*)d_in[8];
    const float* Wo    = (const float*)d_in[9];
    const float* bo    = (const float*)d_in[10];
    float* out = (float*)d_out;

    float *pQ, *pK, *pV, *pA;
    cudaGetSymbolAddress((void**)&pQ, g_Q);
    cudaGetSymbolAddress((void**)&pK, g_K);
    cudaGetSymbolAddress((void**)&pV, g_V);
    cudaGetSymbolAddress((void**)&pA, g_Attn);

    cudaFuncSetAttribute(gemm_mma<true>,
                         cudaFuncAttributeMaxDynamicSharedMemorySize, GEMM_SMEM);
    cudaFuncSetAttribute(gemm_mma<false>,
                         cudaFuncAttributeMaxDynamicSharedMemorySize, GEMM_SMEM);
    cudaFuncSetAttribute(attn_mma,
                         cudaFuncAttributeMaxDynamicSharedMemorySize, ATTN_SMEM);

    dim3 gemm_grid(D_MODEL / 128, MTOT / 128);   // (8, 32)
    const float qscale = 0.125f;                 // 1/sqrt(64)

    gemm_mma<true><<<gemm_grid, 256, GEMM_SMEM>>>(query, Wq, bq, qscale, pQ);
    gemm_mma<true><<<gemm_grid, 256, GEMM_SMEM>>>(key,   Wk, bk, 1.f,    pK);
    gemm_mma<true><<<gemm_grid, 256, GEMM_SMEM>>>(value, Wv, bv, 1.f,    pV);

    dim3 attn_grid(SEQ / 128, NHEAD, BATCH);     // (16, 16, 2)
    attn_mma<<<attn_grid, 256, ATTN_SMEM>>>(pQ, pK, pV, pA);

    gemm_mma<false><<<gemm_grid, 256, GEMM_SMEM>>>(pA, Wo, bo, 1.f, out);
}